// round 3
// baseline (speedup 1.0000x reference)
#include <cuda_runtime.h>
#include <cstdint>

#define NTOK 262144
#define DF 128
#define CC 64
#define TILES 2048
#define GRID 152

// ---- static device scratch (per-CTA partials; fully overwritten every run) ----
__device__ float  g_Fpart[GRID * CC * DF];
__device__ int    g_cntpart[GRID * CC];
__device__ double g_f2part[GRID];
__device__ double g_s2part[32];

// ---- shared memory byte offsets ----
#define SM_FKM   0          // float[128*128]  k-major feature tile (xor-swizzled)
#define SM_CP    65536      // ull[128*32]     center class-pairs, k-major f32x2
#define SM_F     98304      // float[64*128]   per-CTA class feature sums
#define SM_C2    131072     // float[64]
#define SM_F2    131328     // float[128]
#define SM_LBL   131840     // int[128]
#define SM_CNT   132352     // int[64]
#define SM_CNTT  132608     // int[64]
#define SM_LIST  132864     // u8[64*128]
#define SM_DRED  141056     // double[128]
#define SM_TOTAL 142080

// ---- packed f32x2 helpers (sm_100+) ----
__device__ __forceinline__ unsigned long long pack2(float x) {
    unsigned long long r; unsigned u = __float_as_uint(x);
    asm("mov.b64 %0, {%1, %1};" : "=l"(r) : "r"(u));
    return r;
}
__device__ __forceinline__ unsigned long long pack2b(float x, float y) {
    unsigned long long r;
    asm("mov.b64 %0, {%1, %2};" : "=l"(r) : "r"(__float_as_uint(x)), "r"(__float_as_uint(y)));
    return r;
}
__device__ __forceinline__ void fma2(unsigned long long& acc, unsigned long long a, unsigned long long b) {
    asm("fma.rn.f32x2 %0, %1, %2, %0;" : "+l"(acc) : "l"(a), "l"(b));
}
__device__ __forceinline__ void unpack2(unsigned long long v, float& lo, float& hi) {
    unsigned a, b;
    asm("mov.b64 {%0, %1}, %2;" : "=r"(a), "=r"(b) : "l"(v));
    lo = __uint_as_float(a); hi = __uint_as_float(b);
}

// ============================================================
// main persistent kernel
// ============================================================
__global__ void __launch_bounds__(256, 1)
k_main(const float* __restrict__ feature, const int* __restrict__ label,
       const float* __restrict__ centers, float* __restrict__ out)
{
    extern __shared__ char sm[];
    float*              f_km    = (float*)(sm + SM_FKM);
    unsigned long long* cpair   = (unsigned long long*)(sm + SM_CP);
    float*              F_sm    = (float*)(sm + SM_F);
    float*              c2_sm   = (float*)(sm + SM_C2);
    float*              f2_sm   = (float*)(sm + SM_F2);
    int*                lbl_sm  = (int*)(sm + SM_LBL);
    int*                cnt_sm  = (int*)(sm + SM_CNT);
    int*                cntt_sm = (int*)(sm + SM_CNTT);
    unsigned char*      list_sm = (unsigned char*)(sm + SM_LIST);
    double*             dred    = (double*)(sm + SM_DRED);

    const int tid = threadIdx.x;
    const int bid = blockIdx.x;
    const int w = tid >> 5, l = tid & 31;
    const int cg = w & 3;          // class group: classes 16cg..16cg+15 (pairs 8cg..8cg+7)
    const int tg = w >> 2;         // token half
    const int t0 = tg * 64 + 2 * l;
    const int c0 = cg * 16;

    // ---- one-time init ----
    for (int i = tid; i < CC * DF; i += 256) F_sm[i] = 0.f;
    if (tid < CC) cntt_sm[tid] = 0;
    for (int p = tid; p < DF * 32; p += 256) {
        int k = p >> 5, pr = p & 31;
        cpair[k * 32 + pr] = pack2b(centers[(2 * pr) * DF + k], centers[(2 * pr + 1) * DF + k]);
    }
    if (tid < CC) {
        float s = 0.f;
        for (int k = 0; k < DF; k++) { float c = centers[tid * DF + k]; s += c * c; }
        c2_sm[tid] = s;
    }
    double f2acc = 0.0;
    __syncthreads();

    float* distp = out + 1 + CC * DF;   // out + 8193

    for (int tile = bid; tile < TILES; tile += gridDim.x) {
        __syncthreads();  // prior tile's phase-3 readers done before smem reuse
        const int base = tile * 128;

        if (tid < 128)      lbl_sm[tid] = label[base + tid] & (CC - 1);
        else if (tid < 192) cnt_sm[tid - 128] = 0;

        // ---- load + transpose (xor swizzle) + per-token |f|^2 ----
        #pragma unroll
        for (int i = 0; i < 16; i++) {
            int v = i * 256 + tid;           // warp covers one full token row
            int tok = v >> 5, kq = v & 31;
            const float4 f4 = *(const float4*)&feature[(size_t)(base + tok) * DF + kq * 4];
            float s = f4.x * f4.x + f4.y * f4.y + f4.z * f4.z + f4.w * f4.w;
            #pragma unroll
            for (int o = 16; o; o >>= 1) s += __shfl_xor_sync(0xffffffffu, s, o);
            if (l == 0) f2_sm[tok] = s;
            int col = tok ^ ((kq & 7) << 2); // swizzle: col(t,k) = t ^ 4*((k>>2)&7)
            f_km[(4 * kq + 0) * 128 + col] = f4.x;
            f_km[(4 * kq + 1) * 128 + col] = f4.y;
            f_km[(4 * kq + 2) * 128 + col] = f4.z;
            f_km[(4 * kq + 3) * 128 + col] = f4.w;
        }
        __syncthreads();

        // ---- per-tile class row lists ----
        if (tid < 128) {
            int c = lbl_sm[tid];
            int idx = atomicAdd(&cnt_sm[c], 1);
            list_sm[c * 128 + idx] = (unsigned char)tid;
        }

        // ---- GEMM: dot(f_t, c_c), 2 tokens x 16 classes per thread, f32x2 ----
        unsigned long long acc[2][8];
        #pragma unroll
        for (int a = 0; a < 2; a++)
            #pragma unroll
            for (int j = 0; j < 8; j++) acc[a][j] = 0ull;

        #pragma unroll 4
        for (int k = 0; k < 128; k++) {
            int m = (k >> 2) & 7;
            const float2 fv = *(const float2*)&f_km[k * 128 + (t0 ^ (m << 2))];
            unsigned long long fa = pack2(fv.x), fb = pack2(fv.y);
            const ulonglong2* cp2 = (const ulonglong2*)&cpair[k * 32 + cg * 8];
            #pragma unroll
            for (int jj = 0; jj < 4; jj++) {
                ulonglong2 cc = cp2[jj];
                fma2(acc[0][2 * jj + 0], fa, cc.x);
                fma2(acc[1][2 * jj + 0], fb, cc.x);
                fma2(acc[0][2 * jj + 1], fa, cc.y);
                fma2(acc[1][2 * jj + 1], fb, cc.y);
            }
        }

        // ---- epilogue: dist = f2 + c2 - 2*dot ----
        #pragma unroll
        for (int a = 0; a < 2; a++) {
            int t = t0 + a;
            float ft2 = f2_sm[t];
            float* dp = distp + (size_t)(base + t) * CC + c0;
            #pragma unroll
            for (int j = 0; j < 8; j++) {
                float lo, hi; unpack2(acc[a][j], lo, hi);
                dp[2 * j + 0] = fmaf(-2.f, lo, ft2 + c2_sm[c0 + 2 * j + 0]);
                dp[2 * j + 1] = fmaf(-2.f, hi, ft2 + c2_sm[c0 + 2 * j + 1]);
            }
        }
        __syncthreads();

        // ---- phase 3: F[c][d] accumulation (thread owns class c, d-quarter q) ----
        {
            const int c = tid >> 2, q = tid & 3;
            const int n = cnt_sm[c];
            const unsigned char* lst = list_sm + c * 128;
            float s[32];
            #pragma unroll
            for (int dd = 0; dd < 32; dd++) s[dd] = 0.f;
            for (int i = 0; i < n; i++) {
                int r = lst[i];
                #pragma unroll
                for (int dd = 0; dd < 32; dd++) {
                    // f[r][d] at f_km[d*128 + (r ^ ((d>>2&7)<<2))]; d = q*32+dd -> xor = dd&28
                    s[dd] += f_km[(q * 32 + dd) * 128 + (r ^ (dd & 28))];
                }
            }
            float* Fp = F_sm + c * DF + q * 32;
            #pragma unroll
            for (int dd = 0; dd < 32; dd++) Fp[dd] += s[dd];
        }
        if (tid < CC)  cntt_sm[tid] += cnt_sm[tid];
        if (tid < 128) f2acc += (double)f2_sm[tid];
    }

    // ---- flush per-CTA partials (deterministic: own slot, no atomics) ----
    __syncthreads();
    for (int i = tid; i < CC * DF; i += 256) g_Fpart[bid * CC * DF + i] = F_sm[i];
    if (tid < CC)  g_cntpart[bid * CC + tid] = cntt_sm[tid];
    if (tid < 128) dred[tid] = f2acc;
    __syncthreads();
    if (tid == 0) {
        double s = 0.0;
        for (int i = 0; i < 128; i++) s += dred[i];
        g_f2part[bid] = s;
    }
}

// ============================================================
// finalize 1: difference[C,D] + partial s2 = sum(F*centers)
// grid = 32 blocks x 256 threads, one (c,d) per thread
// ============================================================
__global__ void k_final1(const float* __restrict__ centers, float* __restrict__ out)
{
    __shared__ int cnti[CC];
    __shared__ double dsum[256];
    int tid = threadIdx.x;
    if (tid < CC) {
        int s = 0;
        for (int b = 0; b < GRID; b++) s += g_cntpart[b * CC + tid];
        cnti[tid] = s;
    }
    __syncthreads();
    int i = blockIdx.x * 256 + tid;            // 0..8191
    double F = 0.0;
    for (int b = 0; b < GRID; b++) F += (double)g_Fpart[b * CC * DF + i];
    int c = i >> 7;
    double cen = (double)centers[i];
    int n = cnti[c]; int ncl = n > 0 ? n : 1;
    out[1 + i] = (float)(((double)n * cen - F) / (double)ncl);
    dsum[tid] = F * cen;
    __syncthreads();
    for (int off = 128; off; off >>= 1) {
        if (tid < off) dsum[tid] += dsum[tid + off];
        __syncthreads();
    }
    if (tid == 0) g_s2part[blockIdx.x] = dsum[0];
}

// ============================================================
// finalize 2: center_loss scalar
// ============================================================
__global__ void k_final2(const float* __restrict__ centers, float* __restrict__ out)
{
    __shared__ double sred[64];
    int tid = threadIdx.x;
    double s3 = 0.0;
    if (tid < CC) {
        int n = 0;
        for (int b = 0; b < GRID; b++) n += g_cntpart[b * CC + tid];
        double c2 = 0.0;
        for (int k = 0; k < DF; k++) { double cv = (double)centers[tid * DF + k]; c2 += cv * cv; }
        s3 = (double)n * c2;
    }
    sred[tid] = s3;
    __syncthreads();
    for (int off = 32; off; off >>= 1) {
        if (tid < off) sred[tid] += sred[tid + off];
        __syncthreads();
    }
    if (tid == 0) {
        double s1 = 0.0;
        for (int b = 0; b < GRID; b++) s1 += g_f2part[b];
        double s2 = 0.0;
        for (int b = 0; b < 32; b++) s2 += g_s2part[b];
        out[0] = (float)((s1 - 2.0 * s2 + sred[0]) / ((double)NTOK * (double)DF));
    }
}

// ============================================================
extern "C" void kernel_launch(void* const* d_in, const int* in_sizes, int n_in,
                              void* d_out, int out_size)
{
    const float* feature = (const float*)d_in[0];
    const int*   label   = (const int*)d_in[1];
    const float* centers = (const float*)d_in[2];
    float*       out     = (float*)d_out;

    cudaFuncSetAttribute(k_main, cudaFuncAttributeMaxDynamicSharedMemorySize, SM_TOTAL);
    k_main<<<GRID, 256, SM_TOTAL>>>(feature, label, centers, out);
    k_final1<<<32, 256>>>(centers, out);
    k_final2<<<1, 64>>>(centers, out);
}

// round 5
// speedup vs baseline: 1.8572x; 1.8572x over previous
#include <cuda_runtime.h>
#include <cstdint>

#define NTOK 262144
#define DF 128
#define CC 64
#define TILES 2048
#define GRID 152
#define NTHR 512

// ---- static device scratch (per-CTA partials) ----
__device__ float  g_Fpart[GRID * CC * DF];
__device__ int    g_cntpart[GRID * CC];
__device__ double g_f2part[GRID];
__device__ double g_s2part[32];

// ---- shared memory byte offsets ----
#define SM_ATF   0          // float[128*132] tf32-rounded feature tile
#define SM_CTF   67584      // float[64*132]  tf32-rounded centers
#define SM_FSUM  101376     // float[64*132]  per-CTA class sums
#define SM_STAGE 135168     // float[128*66]  distance staging (aligned float2)
#define SM_F2    168960     // float[128] (+pad)
#define SM_C2    169472     // float[64]
#define SM_LBL   169728     // int[128]
#define SM_CNT   170240     // int[64]
#define SM_CNTT  170496     // int[64]
#define SM_LIST  170752     // u8[64*128]
#define SM_TOTAL 178944

__device__ __forceinline__ float tf32r(float x) {
    unsigned u;
    asm("cvt.rna.tf32.f32 %0, %1;" : "=r"(u) : "f"(x));
    return __uint_as_float(u);
}
__device__ __forceinline__ void mma_tf32(float* d, unsigned a0, unsigned a1,
                                         unsigned a2, unsigned a3,
                                         unsigned b0, unsigned b1) {
    asm volatile(
        "mma.sync.aligned.m16n8k8.row.col.f32.tf32.tf32.f32 "
        "{%0,%1,%2,%3}, {%4,%5,%6,%7}, {%8,%9}, {%0,%1,%2,%3};"
        : "+f"(d[0]), "+f"(d[1]), "+f"(d[2]), "+f"(d[3])
        : "r"(a0), "r"(a1), "r"(a2), "r"(a3), "r"(b0), "r"(b1));
}

// ============================================================
__global__ void __launch_bounds__(NTHR, 1)
k_main(const float* __restrict__ feature, const int* __restrict__ label,
       const float* __restrict__ centers, float* __restrict__ out)
{
    extern __shared__ __align__(16) char sm[];
    float*         atf     = (float*)(sm + SM_ATF);
    float*         ctf     = (float*)(sm + SM_CTF);
    float*         F_sm    = (float*)(sm + SM_FSUM);
    float*         stage   = (float*)(sm + SM_STAGE);
    float*         f2_sm   = (float*)(sm + SM_F2);
    float*         c2_sm   = (float*)(sm + SM_C2);
    int*           lbl_sm  = (int*)(sm + SM_LBL);
    int*           cnt_sm  = (int*)(sm + SM_CNT);
    int*           cntt_sm = (int*)(sm + SM_CNTT);
    unsigned char* list_sm = (unsigned char*)(sm + SM_LIST);

    const int tid = threadIdx.x, bid = blockIdx.x;
    const int w = tid >> 5, l = tid & 31;
    const int lq = l >> 2, lr = l & 3;          // quad row / quad lane
    const int mbase = (w >> 2) * 32;            // 4 m-groups of 32 tokens
    const int nbase = (w & 3) * 16;             // 4 n-groups of 16 classes

    // ---- one-time init ----
    for (int i = tid; i < CC * 132; i += NTHR) F_sm[i] = 0.f;
    for (int i = tid; i < CC * DF; i += NTHR) {
        int n = i >> 7, k = i & 127;
        ctf[n * 132 + k] = tf32r(centers[i]);
    }
    if (tid < CC) {
        float s = 0.f;
        for (int k = 0; k < DF; k++) { float c = centers[tid * DF + k]; s += c * c; }
        c2_sm[tid] = s;
        cntt_sm[tid] = 0;
    }
    __syncthreads();

    // ---- persistent B fragments: classes nbase..nbase+15, all K ----
    unsigned bfr[16][2][2];
    #pragma unroll
    for (int kc = 0; kc < 16; kc++)
        #pragma unroll
        for (int j = 0; j < 2; j++) {
            const float* cp = &ctf[(nbase + j * 8 + lq) * 132 + kc * 8 + lr];
            bfr[kc][j][0] = __float_as_uint(cp[0]);
            bfr[kc][j][1] = __float_as_uint(cp[4]);
        }

    double f2acc = 0.0;

    for (int tile = bid; tile < TILES; tile += GRID) {
        __syncthreads();                         // S1: smem reuse safe
        const int base = tile * 128;

        if (tid < 128)      lbl_sm[tid] = label[base + tid] & (CC - 1);
        else if (tid < 192) cnt_sm[tid - 128] = 0;

        // ---- load, exact f2, tf32-round, store tile ----
        #pragma unroll
        for (int it = 0; it < 8; it++) {
            const int v = it * NTHR + tid;
            const int tok = v >> 5, i4 = v & 31;    // warp = one token row
            float4 f4 = *(const float4*)&feature[(size_t)(base + tok) * DF + i4 * 4];
            float s = f4.x * f4.x + f4.y * f4.y + f4.z * f4.z + f4.w * f4.w;
            #pragma unroll
            for (int o = 16; o; o >>= 1) s += __shfl_xor_sync(0xffffffffu, s, o);
            if (l == 0) f2_sm[tok] = s;
            f4.x = tf32r(f4.x); f4.y = tf32r(f4.y);
            f4.z = tf32r(f4.z); f4.w = tf32r(f4.w);
            *(float4*)&atf[tok * 132 + i4 * 4] = f4;
        }
        __syncthreads();                         // S2: tile + labels visible

        // ---- per-tile class row lists ----
        if (tid < 128) {
            int c = lbl_sm[tid];
            int idx = atomicAdd(&cnt_sm[c], 1);
            list_sm[c * 128 + idx] = (unsigned char)tid;
        }

        // ---- GEMM: 32 tokens x 16 classes per warp, TF32 HMMA ----
        float acc[2][2][4];
        #pragma unroll
        for (int mi = 0; mi < 2; mi++)
            #pragma unroll
            for (int j = 0; j < 2; j++)
                #pragma unroll
                for (int e = 0; e < 4; e++) acc[mi][j][e] = 0.f;

        #pragma unroll
        for (int kc = 0; kc < 16; kc++) {
            #pragma unroll
            for (int mi = 0; mi < 2; mi++) {
                const float* ap = &atf[(mbase + mi * 16 + lq) * 132 + kc * 8 + lr];
                unsigned a0 = __float_as_uint(ap[0]);
                unsigned a2 = __float_as_uint(ap[4]);
                unsigned a1 = __float_as_uint(ap[8 * 132]);
                unsigned a3 = __float_as_uint(ap[8 * 132 + 4]);
                mma_tf32(acc[mi][0], a0, a1, a2, a3, bfr[kc][0][0], bfr[kc][0][1]);
                mma_tf32(acc[mi][1], a0, a1, a2, a3, bfr[kc][1][0], bfr[kc][1][1]);
            }
        }

        // ---- epilogue: dist = f2 + c2 - 2*dot -> stage (stride 66) ----
        #pragma unroll
        for (int mi = 0; mi < 2; mi++) {
            const int r0 = mbase + mi * 16 + lq;
            const float ft0 = f2_sm[r0], ft1 = f2_sm[r0 + 8];
            #pragma unroll
            for (int j = 0; j < 2; j++) {
                const int n0 = nbase + j * 8 + lr * 2;
                const float cA = c2_sm[n0], cB = c2_sm[n0 + 1];
                float2 v0, v1;
                v0.x = fmaf(-2.f, acc[mi][j][0], ft0 + cA);
                v0.y = fmaf(-2.f, acc[mi][j][1], ft0 + cB);
                v1.x = fmaf(-2.f, acc[mi][j][2], ft1 + cA);
                v1.y = fmaf(-2.f, acc[mi][j][3], ft1 + cB);
                *(float2*)&stage[r0 * 66 + n0] = v0;
                *(float2*)&stage[(r0 + 8) * 66 + n0] = v1;
            }
        }
        __syncthreads();                         // S3: stage + lists ready

        // ---- phase 3: per-class feature sums (thread = class x d-eighth) ----
        {
            const int c = tid >> 3, q = tid & 7;
            const int n = cnt_sm[c];
            const unsigned char* lst = list_sm + c * 128;
            float s[16];
            #pragma unroll
            for (int dd = 0; dd < 16; dd++) s[dd] = 0.f;
            for (int i = 0; i < n; i++) {
                const float* fp = &atf[lst[i] * 132 + q * 16];
                #pragma unroll
                for (int p = 0; p < 4; p++) {
                    float4 v = *(const float4*)&fp[p * 4];
                    s[4 * p + 0] += v.x; s[4 * p + 1] += v.y;
                    s[4 * p + 2] += v.z; s[4 * p + 3] += v.w;
                }
            }
            float* Fp = F_sm + c * 132 + q * 16;
            #pragma unroll
            for (int dd = 0; dd < 16; dd++) Fp[dd] += s[dd];
        }
        if (tid < CC)  cntt_sm[tid] += cnt_sm[tid];
        if (tid < 128) f2acc += (double)f2_sm[tid];

        // ---- flat aligned store: out + 8193 + tile*8192 ----
        float* gdst = out + 1 + CC * DF + (size_t)tile * 8192;
        if (tid < 4) {
            if (tid < 3) gdst[tid] = stage[tid];
            else         gdst[8191] = stage[127 * 66 + 63];
        }
        for (int qq = tid; qq < 2047; qq += NTHR) {
            const int j0 = 3 + 4 * qq;
            float4 v;
            v.x = stage[((j0 + 0) >> 6) * 66 + ((j0 + 0) & 63)];
            v.y = stage[((j0 + 1) >> 6) * 66 + ((j0 + 1) & 63)];
            v.z = stage[((j0 + 2) >> 6) * 66 + ((j0 + 2) & 63)];
            v.w = stage[((j0 + 3) >> 6) * 66 + ((j0 + 3) & 63)];
            *(float4*)(gdst + j0) = v;
        }
    }

    // ---- flush per-CTA partials (deterministic slots) ----
    __syncthreads();
    for (int i = tid; i < CC * DF; i += NTHR)
        g_Fpart[bid * CC * DF + i] = F_sm[(i >> 7) * 132 + (i & 127)];
    if (tid < CC) g_cntpart[bid * CC + tid] = cntt_sm[tid];
    {
        double* dred = (double*)(sm + SM_STAGE);
        dred[tid] = (tid < 128) ? f2acc : 0.0;
        __syncthreads();
        if (tid == 0) {
            double s = 0.0;
            for (int i = 0; i < 128; i++) s += dred[i];
            g_f2part[bid] = s;
        }
    }
}

// ============================================================
__global__ void k_final1(const float* __restrict__ centers, float* __restrict__ out)
{
    __shared__ int cnti[CC];
    __shared__ double dsum[256];
    int tid = threadIdx.x;
    if (tid < CC) {
        int s = 0;
        for (int b = 0; b < GRID; b++) s += g_cntpart[b * CC + tid];
        cnti[tid] = s;
    }
    __syncthreads();
    int i = blockIdx.x * 256 + tid;
    double F = 0.0;
    for (int b = 0; b < GRID; b++) F += (double)g_Fpart[b * CC * DF + i];
    int c = i >> 7;
    double cen = (double)centers[i];
    int n = cnti[c]; int ncl = n > 0 ? n : 1;
    out[1 + i] = (float)(((double)n * cen - F) / (double)ncl);
    dsum[tid] = F * cen;
    __syncthreads();
    for (int off = 128; off; off >>= 1) {
        if (tid < off) dsum[tid] += dsum[tid + off];
        __syncthreads();
    }
    if (tid == 0) g_s2part[blockIdx.x] = dsum[0];
}

__global__ void k_final2(const float* __restrict__ centers, float* __restrict__ out)
{
    __shared__ double sred[64];
    int tid = threadIdx.x;
    double s3 = 0.0;
    if (tid < CC) {
        int n = 0;
        for (int b = 0; b < GRID; b++) n += g_cntpart[b * CC + tid];
        double c2 = 0.0;
        for (int k = 0; k < DF; k++) { double cv = (double)centers[tid * DF + k]; c2 += cv * cv; }
        s3 = (double)n * c2;
    }
    sred[tid] = s3;
    __syncthreads();
    for (int off = 32; off; off >>= 1) {
        if (tid < off) sred[tid] += sred[tid + off];
        __syncthreads();
    }
    if (tid == 0) {
        double s1 = 0.0;
        for (int b = 0; b < GRID; b++) s1 += g_f2part[b];
        double s2 = 0.0;
        for (int b = 0; b < 32; b++) s2 += g_s2part[b];
        out[0] = (float)((s1 - 2.0 * s2 + sred[0]) / ((double)NTOK * (double)DF));
    }
}

// ============================================================
extern "C" void kernel_launch(void* const* d_in, const int* in_sizes, int n_in,
                              void* d_out, int out_size)
{
    const float* feature = (const float*)d_in[0];
    const int*   label   = (const int*)d_in[1];
    const float* centers = (const float*)d_in[2];
    float*       out     = (float*)d_out;

    cudaFuncSetAttribute(k_main, cudaFuncAttributeMaxDynamicSharedMemorySize, SM_TOTAL);
    k_main<<<GRID, NTHR, SM_TOTAL>>>(feature, label, centers, out);
    k_final1<<<32, 256>>>(centers, out);
    k_final2<<<1, 64>>>(centers, out);
}